// round 1
// baseline (speedup 1.0000x reference)
#include <cuda_runtime.h>
#include <math.h>

#define B 64
#define H 1024
#define T 1024
#define V 32000

// ---------------- scratch (alloc-free: __device__ globals) ----------------
__device__ float g_emb[B * H];
__device__ float g_gx[B * 3 * H];
__device__ float g_gh[B * 3 * H];
__device__ float g_hnew[B * H];
__device__ float g_scores[B * T];
__device__ float g_attn[B * T];
__device__ float g_ctxpart[B * 8 * H];
__device__ float g_concat_in[B * 2 * H];
__device__ float g_concat_out[B * H];

typedef unsigned long long u64;

__device__ __forceinline__ u64 pack2(float lo, float hi) {
    u64 r;
    asm("mov.b64 %0, {%1, %2};" : "=l"(r) : "f"(lo), "f"(hi));
    return r;
}
__device__ __forceinline__ void unpack2(u64 v, float &lo, float &hi) {
    asm("mov.b64 {%0, %1}, %2;" : "=f"(lo), "=f"(hi) : "l"(v));
}
#define FMA2(d, a, b, c) \
    asm("fma.rn.f32x2 %0, %1, %2, %3;" : "=l"(d) : "l"(a), "l"(b), "l"(c))

// ---------------------------------------------------------------------------
// Generic GEMM: C[n*M + m] = sum_k W[m*K + k] * X[n*K + k] + bias[m]
// N fixed at 64 (batch). act==1 -> tanh. f32x2 packed accumulators over n.
// Block: 256 threads, 64(m) x 64(n) tile, thread tile 4m x 4n.
// ---------------------------------------------------------------------------
__global__ void __launch_bounds__(256) gemm_nt64(
    const float *__restrict__ W, const float *__restrict__ X,
    const float *__restrict__ bias, float *__restrict__ C,
    int M, int K, int act) {
    __shared__ float As[16][64];
    __shared__ float Xs[16][64];
    const int tid = threadIdx.x;
    const int mBase = blockIdx.x * 64;
    const int tx = tid & 15;       // n group
    const int ty = tid >> 4;       // m group
    const int lm = tid & 63;       // load row within tile
    const int lk4 = (tid >> 6) << 2;  // load k offset (0,4,8,12)

    const float *Wp = W + (size_t)(mBase + lm) * K + lk4;
    const float *Xp = X + (size_t)lm * K + lk4;

    float4 wreg = *(const float4 *)Wp;
    float4 xreg = *(const float4 *)Xp;

    u64 acc[4][2];
#pragma unroll
    for (int i = 0; i < 4; i++) { acc[i][0] = 0ull; acc[i][1] = 0ull; }

    const int NT = K >> 4;
    for (int kt = 0; kt < NT; ++kt) {
        __syncthreads();
        As[lk4 + 0][lm] = wreg.x; As[lk4 + 1][lm] = wreg.y;
        As[lk4 + 2][lm] = wreg.z; As[lk4 + 3][lm] = wreg.w;
        Xs[lk4 + 0][lm] = xreg.x; Xs[lk4 + 1][lm] = xreg.y;
        Xs[lk4 + 2][lm] = xreg.z; Xs[lk4 + 3][lm] = xreg.w;
        __syncthreads();
        if (kt + 1 < NT) {  // register prefetch of next tile overlaps compute
            wreg = *(const float4 *)(Wp + (kt + 1) * 16);
            xreg = *(const float4 *)(Xp + (kt + 1) * 16);
        }
#pragma unroll
        for (int k = 0; k < 16; k++) {
            float4 a = *(const float4 *)&As[k][ty << 2];
            u64 xp0 = *(const u64 *)&Xs[k][tx << 2];
            u64 xp1 = *(const u64 *)&Xs[k][(tx << 2) + 2];
            u64 a0 = pack2(a.x, a.x), a1 = pack2(a.y, a.y);
            u64 a2 = pack2(a.z, a.z), a3 = pack2(a.w, a.w);
            FMA2(acc[0][0], a0, xp0, acc[0][0]);
            FMA2(acc[0][1], a0, xp1, acc[0][1]);
            FMA2(acc[1][0], a1, xp0, acc[1][0]);
            FMA2(acc[1][1], a1, xp1, acc[1][1]);
            FMA2(acc[2][0], a2, xp0, acc[2][0]);
            FMA2(acc[2][1], a2, xp1, acc[2][1]);
            FMA2(acc[3][0], a3, xp0, acc[3][0]);
            FMA2(acc[3][1], a3, xp1, acc[3][1]);
        }
    }

    float cv[4][4];  // [mi][nj]
#pragma unroll
    for (int mi = 0; mi < 4; mi++) {
        unpack2(acc[mi][0], cv[mi][0], cv[mi][1]);
        unpack2(acc[mi][1], cv[mi][2], cv[mi][3]);
    }
    float4 bz = *(const float4 *)(bias + mBase + (ty << 2));
#pragma unroll
    for (int mi = 0; mi < 4; mi++) {
        float bb = (&bz.x)[mi];
#pragma unroll
        for (int nj = 0; nj < 4; nj++) {
            float v = cv[mi][nj] + bb;
            if (act) v = tanhf(v);
            cv[mi][nj] = v;
        }
    }
#pragma unroll
    for (int nj = 0; nj < 4; nj++) {
        float4 o = make_float4(cv[0][nj], cv[1][nj], cv[2][nj], cv[3][nj]);
        *(float4 *)(C + (size_t)((tx << 2) + nj) * M + mBase + (ty << 2)) = o;
    }
}

// ---------------------------------------------------------------------------
// Embedding gather: g_emb[b, :] = emb_table[seq[b], :]
// ---------------------------------------------------------------------------
__global__ void __launch_bounds__(256) gather_emb(
    const int *__restrict__ seq, const float *__restrict__ emb_table) {
    int idx = blockIdx.x * 256 + threadIdx.x;  // over B*H/4
    int b = idx >> 8;                          // 256 float4 per row
    int h4 = (idx & 255) << 2;
    int row = seq[b];
    *(float4 *)(g_emb + b * H + h4) =
        *(const float4 *)(emb_table + (size_t)row * H + h4);
}

// ---------------------------------------------------------------------------
// GRU gate combine: reads g_gx/g_gh, writes h_new everywhere it's needed
// ---------------------------------------------------------------------------
__global__ void __launch_bounds__(256) gru_combine(
    const float *__restrict__ hprev, float *__restrict__ out_hidden) {
    int idx = blockIdx.x * 256 + threadIdx.x;  // B*H
    int b = idx >> 10, i = idx & 1023;
    const float *gx = g_gx + b * 3072;
    const float *gh = g_gh + b * 3072;
    float xr = gx[i], xz = gx[1024 + i], xn = gx[2048 + i];
    float hr = gh[i], hz = gh[1024 + i], hn = gh[2048 + i];
    float hp = hprev[idx];
    float r = 1.f / (1.f + expf(-(xr + hr)));
    float z = 1.f / (1.f + expf(-(xz + hz)));
    float n = tanhf(xn + r * hn);
    float h = (1.f - z) * n + z * hp;
    g_hnew[idx] = h;
    out_hidden[idx] = h;
    g_concat_in[b * 2048 + i] = h;
}

// ---------------------------------------------------------------------------
// Attention scores: scores[b,t] = dot(h_new[b,:], enc[t,b,:])
// grid (T/64, B); 8 warps x 8 t each; coalesced float4 loads of enc rows.
// ---------------------------------------------------------------------------
__global__ void __launch_bounds__(256) scores_kernel(const float *__restrict__ enc) {
    const int b = blockIdx.y;
    const int t0 = blockIdx.x * 64;
    __shared__ float hs[H];
    int tid = threadIdx.x;
    *(float4 *)(hs + tid * 4) = *(const float4 *)(g_hnew + b * H + tid * 4);
    __syncthreads();
    const int warp = tid >> 5, lane = tid & 31;
#pragma unroll
    for (int it = 0; it < 8; it++) {
        int t = t0 + warp * 8 + it;
        const float *e = enc + ((size_t)t * B + b) * H;
        float acc = 0.f;
#pragma unroll
        for (int i = 0; i < 8; i++) {
            int h = i * 128 + lane * 4;
            float4 ev = *(const float4 *)(e + h);
            float4 hv = *(const float4 *)(hs + h);
            acc += ev.x * hv.x + ev.y * hv.y + ev.z * hv.z + ev.w * hv.w;
        }
#pragma unroll
        for (int o = 16; o; o >>= 1) acc += __shfl_xor_sync(0xffffffffu, acc, o);
        if (!lane) g_scores[b * T + t] = acc;
    }
}

// ---------------------------------------------------------------------------
// Softmax over T per batch row; writes both scratch attn and d_out attn region
// ---------------------------------------------------------------------------
__global__ void __launch_bounds__(256) softmax_kernel(float *__restrict__ attn_out) {
    const int b = blockIdx.x;
    const int tid = threadIdx.x;
    const int lane = tid & 31, wid = tid >> 5;
    __shared__ float red[8];
    float4 s = *(const float4 *)(g_scores + b * T + tid * 4);
    float m = fmaxf(fmaxf(s.x, s.y), fmaxf(s.z, s.w));
#pragma unroll
    for (int o = 16; o; o >>= 1) m = fmaxf(m, __shfl_xor_sync(0xffffffffu, m, o));
    if (!lane) red[wid] = m;
    __syncthreads();
    float bm = red[0];
#pragma unroll
    for (int i = 1; i < 8; i++) bm = fmaxf(bm, red[i]);
    float e0 = expf(s.x - bm), e1 = expf(s.y - bm);
    float e2 = expf(s.z - bm), e3 = expf(s.w - bm);
    float ssum = e0 + e1 + e2 + e3;
#pragma unroll
    for (int o = 16; o; o >>= 1) ssum += __shfl_xor_sync(0xffffffffu, ssum, o);
    __syncthreads();
    if (!lane) red[wid] = ssum;
    __syncthreads();
    float tot = 0.f;
#pragma unroll
    for (int i = 0; i < 8; i++) tot += red[i];
    float inv = 1.f / tot;
    float4 p = make_float4(e0 * inv, e1 * inv, e2 * inv, e3 * inv);
    *(float4 *)(g_attn + b * T + tid * 4) = p;
    *(float4 *)(attn_out + b * T + tid * 4) = p;
}

// ---------------------------------------------------------------------------
// Context partial sums: grid (8 t-chunks, B); each block does 128 t's.
// ---------------------------------------------------------------------------
__global__ void __launch_bounds__(256) ctx_partial(const float *__restrict__ enc) {
    const int b = blockIdx.y, c = blockIdx.x;
    const int t0 = c * 128;
    __shared__ float ws[128];
    int tid = threadIdx.x;
    if (tid < 128) ws[tid] = g_attn[b * T + t0 + tid];
    __syncthreads();
    float4 acc = make_float4(0.f, 0.f, 0.f, 0.f);
    int h = tid * 4;
    for (int j = 0; j < 128; j++) {
        float4 e = *(const float4 *)(enc + ((size_t)(t0 + j) * B + b) * H + h);
        float w = ws[j];
        acc.x += w * e.x; acc.y += w * e.y; acc.z += w * e.z; acc.w += w * e.w;
    }
    *(float4 *)(g_ctxpart + (size_t)(b * 8 + c) * H + h) = acc;
}

// ---------------------------------------------------------------------------
// Reduce context partials into concat_in[:, H:2H]
// ---------------------------------------------------------------------------
__global__ void __launch_bounds__(256) ctx_reduce() {
    int idx = blockIdx.x * 256 + threadIdx.x;  // B*H
    int b = idx >> 10, h = idx & 1023;
    float s = 0.f;
#pragma unroll
    for (int j = 0; j < 8; j++) s += g_ctxpart[(size_t)(b * 8 + j) * H + h];
    g_concat_in[b * 2048 + 1024 + h] = s;
}

// ---------------------------------------------------------------------------
extern "C" void kernel_launch(void *const *d_in, const int *in_sizes, int n_in,
                              void *d_out, int out_size) {
    const int *seq     = (const int *)d_in[0];
    const float *hprev = (const float *)d_in[1];
    const float *enc   = (const float *)d_in[2];
    const float *emb   = (const float *)d_in[3];
    const float *w_ih  = (const float *)d_in[4];
    const float *w_hh  = (const float *)d_in[5];
    const float *b_ih  = (const float *)d_in[6];
    const float *b_hh  = (const float *)d_in[7];
    const float *cW    = (const float *)d_in[8];
    const float *cb    = (const float *)d_in[9];
    const float *oW    = (const float *)d_in[10];
    const float *ob    = (const float *)d_in[11];
    float *out = (float *)d_out;

    float *p_emb, *p_gx, *p_gh, *p_cin, *p_cout;
    cudaGetSymbolAddress((void **)&p_emb,  g_emb);
    cudaGetSymbolAddress((void **)&p_gx,   g_gx);
    cudaGetSymbolAddress((void **)&p_gh,   g_gh);
    cudaGetSymbolAddress((void **)&p_cin,  g_concat_in);
    cudaGetSymbolAddress((void **)&p_cout, g_concat_out);

    float *out_hidden = out + (size_t)B * V;               // (1,B,H)
    float *out_attn   = out + (size_t)B * V + (size_t)B * H;  // (B,1,T)

    // 1) embedding gather
    gather_emb<<<(B * H / 4) / 256, 256>>>(seq, emb);
    // 2/3) GRU input & hidden GEMMs: (3H x B) each
    gemm_nt64<<<3 * H / 64, 256>>>(w_ih, p_emb, b_ih, p_gx, 3 * H, H, 0);
    gemm_nt64<<<3 * H / 64, 256>>>(w_hh, hprev, b_hh, p_gh, 3 * H, H, 0);
    // 4) gate combine -> h_new (also writes d_out hidden + concat_in[:, :H])
    gru_combine<<<(B * H) / 256, 256>>>(hprev, out_hidden);
    // 5) attention scores
    scores_kernel<<<dim3(T / 64, B), 256>>>(enc);
    // 6) softmax -> attn (d_out region + scratch)
    softmax_kernel<<<B, 256>>>(out_attn);
    // 7/8) context = attn-weighted sum of encoder outputs
    ctx_partial<<<dim3(8, B), 256>>>(enc);
    ctx_reduce<<<(B * H) / 256, 256>>>();
    // 9) concat GEMM with tanh: (H x B), K = 2H
    gemm_nt64<<<H / 64, 256>>>(cW, p_cin, cb, p_cout, H, 2 * H, 1);
    // 10) output GEMM: (V x B), K = H -> writes d_out[0 : B*V]
    gemm_nt64<<<V / 64, 256>>>(oW, p_cout, ob, out, V, H, 0);
}

// round 2
// speedup vs baseline: 1.1244x; 1.1244x over previous
#include <cuda_runtime.h>
#include <math.h>

#define B 64
#define H 1024
#define T 1024
#define V 32000

#define S_GRU 4   // split-K for GRU gemms (K=1024 -> chunks of 256)
#define S_CAT 16  // split-K for concat gemm (K=2048 -> chunks of 128)

// ---------------- scratch (alloc-free: __device__ globals) ----------------
__device__ float g_emb[B * H];
__device__ float g_gxp[S_GRU * B * 3 * H];
__device__ float g_ghp[S_GRU * B * 3 * H];
__device__ float g_hnew[B * H];
__device__ float g_scores[B * T];
__device__ float g_attn[B * T];
__device__ float g_ctxpart[B * 8 * H];
__device__ float g_concat_in[B * 2 * H];
__device__ float g_cp[S_CAT * B * H];
__device__ float g_concat_out[B * H];

typedef unsigned long long u64;

__device__ __forceinline__ u64 pack2(float lo, float hi) {
    u64 r;
    asm("mov.b64 %0, {%1, %2};" : "=l"(r) : "f"(lo), "f"(hi));
    return r;
}
__device__ __forceinline__ void unpack2(u64 v, float &lo, float &hi) {
    asm("mov.b64 {%0, %1}, %2;" : "=f"(lo), "=f"(hi) : "l"(v));
}
#define FMA2(d, a, b, c) \
    asm("fma.rn.f32x2 %0, %1, %2, %3;" : "=l"(d) : "l"(a), "l"(b), "l"(c))

// ---------------------------------------------------------------------------
// GEMM: C[gy*64*M + n*M + m] = sum_{k in chunk gy} W[m*K+k] * X[n*K+k] (+bias)
// CTA tile 128m x 64n, 256 threads, thread tile 8m x 4n.
// m accumulates in natural u64 pairs from As; x broadcast pairs come from a
// DUPLICATED X smem tile -> zero packing instructions in the inner loop.
// blockIdx.z==1 selects the second (W2,X2,C2) problem (fused GRU launch).
// ---------------------------------------------------------------------------
__global__ void __launch_bounds__(256) gemm128(
    const float *__restrict__ W, const float *__restrict__ X,
    const float *__restrict__ W2, const float *__restrict__ X2,
    const float *__restrict__ bias, float *C, float *C2,
    int M, int K, int kChunk) {
    __shared__ float As[16][128];
    __shared__ float Xd[16][128];
    if (blockIdx.z == 1) { W = W2; X = X2; C = C2; }
    const int tid = threadIdx.x;
    const int mBase = blockIdx.x * 128;
    const int kBase = blockIdx.y * kChunk;
    C += (size_t)blockIdx.y * 64 * M;

    const int ty = tid >> 4;         // m group (0..15) -> 8 m each
    const int tx = tid & 15;         // n group -> 4 n each
    const int lm = tid & 127;        // A loader: m row
    const int lka = (tid >> 7) << 3; // A loader: k off 0/8
    const int ln = tid & 63;         // X loader: n row
    const int lkx = (tid >> 6) << 2; // X loader: k off 0,4,8,12

    const float *Wp = W + (size_t)(mBase + lm) * K + kBase + lka;
    const float *Xp = X + (size_t)ln * K + kBase + lkx;

    float4 wa0 = *(const float4 *)Wp;
    float4 wa1 = *(const float4 *)(Wp + 4);
    float4 xr  = *(const float4 *)Xp;

    u64 acc[4][4];
#pragma unroll
    for (int i = 0; i < 4; i++)
#pragma unroll
        for (int j = 0; j < 4; j++) acc[i][j] = 0ull;

    const int NT = kChunk >> 4;
    for (int kt = 0; kt < NT; ++kt) {
        __syncthreads();
        // A transposed into [k][m]
        As[lka + 0][lm] = wa0.x; As[lka + 1][lm] = wa0.y;
        As[lka + 2][lm] = wa0.z; As[lka + 3][lm] = wa0.w;
        As[lka + 4][lm] = wa1.x; As[lka + 5][lm] = wa1.y;
        As[lka + 6][lm] = wa1.z; As[lka + 7][lm] = wa1.w;
        // X duplicated into [k][2n | 2n+1]
        *(u64 *)&Xd[lkx + 0][2 * ln] = pack2(xr.x, xr.x);
        *(u64 *)&Xd[lkx + 1][2 * ln] = pack2(xr.y, xr.y);
        *(u64 *)&Xd[lkx + 2][2 * ln] = pack2(xr.z, xr.z);
        *(u64 *)&Xd[lkx + 3][2 * ln] = pack2(xr.w, xr.w);
        __syncthreads();
        if (kt + 1 < NT) {
            wa0 = *(const float4 *)(Wp + (kt + 1) * 16);
            wa1 = *(const float4 *)(Wp + (kt + 1) * 16 + 4);
            xr  = *(const float4 *)(Xp + (kt + 1) * 16);
        }
#pragma unroll
        for (int k = 0; k < 16; ++k) {
            const ulonglong2 *ar = (const ulonglong2 *)&As[k][ty << 3];
            ulonglong2 a01 = ar[0], a23 = ar[1];
            const ulonglong2 *xp = (const ulonglong2 *)&Xd[k][tx << 3];
            ulonglong2 x01 = xp[0], x23 = xp[1];
            FMA2(acc[0][0], a01.x, x01.x, acc[0][0]);
            FMA2(acc[0][1], a01.x, x01.y, acc[0][1]);
            FMA2(acc[0][2], a01.x, x23.x, acc[0][2]);
            FMA2(acc[0][3], a01.x, x23.y, acc[0][3]);
            FMA2(acc[1][0], a01.y, x01.x, acc[1][0]);
            FMA2(acc[1][1], a01.y, x01.y, acc[1][1]);
            FMA2(acc[1][2], a01.y, x23.x, acc[1][2]);
            FMA2(acc[1][3], a01.y, x23.y, acc[1][3]);
            FMA2(acc[2][0], a23.x, x01.x, acc[2][0]);
            FMA2(acc[2][1], a23.x, x01.y, acc[2][1]);
            FMA2(acc[2][2], a23.x, x23.x, acc[2][2]);
            FMA2(acc[2][3], a23.x, x23.y, acc[2][3]);
            FMA2(acc[3][0], a23.y, x01.x, acc[3][0]);
            FMA2(acc[3][1], a23.y, x01.y, acc[3][1]);
            FMA2(acc[3][2], a23.y, x23.x, acc[3][2]);
            FMA2(acc[3][3], a23.y, x23.y, acc[3][3]);
        }
    }

    // epilogue: acc[mp][nj] -> m = mBase + ty*8 + mp*2 + {0,1}
    float cv[8][4];
#pragma unroll
    for (int mp = 0; mp < 4; mp++)
#pragma unroll
        for (int nj = 0; nj < 4; nj++)
            unpack2(acc[mp][nj], cv[mp * 2][nj], cv[mp * 2 + 1][nj]);

    float bb[8];
    if (bias) {
        float4 b0 = *(const float4 *)(bias + mBase + (ty << 3));
        float4 b1 = *(const float4 *)(bias + mBase + (ty << 3) + 4);
        bb[0] = b0.x; bb[1] = b0.y; bb[2] = b0.z; bb[3] = b0.w;
        bb[4] = b1.x; bb[5] = b1.y; bb[6] = b1.z; bb[7] = b1.w;
    } else {
#pragma unroll
        for (int i = 0; i < 8; i++) bb[i] = 0.f;
    }
#pragma unroll
    for (int nj = 0; nj < 4; nj++) {
        float *cp = C + (size_t)((tx << 2) + nj) * M + mBase + (ty << 3);
        float4 v0 = make_float4(cv[0][nj] + bb[0], cv[1][nj] + bb[1],
                                cv[2][nj] + bb[2], cv[3][nj] + bb[3]);
        float4 v1 = make_float4(cv[4][nj] + bb[4], cv[5][nj] + bb[5],
                                cv[6][nj] + bb[6], cv[7][nj] + bb[7]);
        *(float4 *)cp = v0;
        *(float4 *)(cp + 4) = v1;
    }
}

// ---------------------------------------------------------------------------
// Embedding gather
// ---------------------------------------------------------------------------
__global__ void __launch_bounds__(256) gather_emb(
    const int *__restrict__ seq, const float *__restrict__ emb_table) {
    int idx = blockIdx.x * 256 + threadIdx.x;  // B*H/4
    int b = idx >> 8;
    int h4 = (idx & 255) << 2;
    int row = seq[b];
    *(float4 *)(g_emb + b * H + h4) =
        *(const float4 *)(emb_table + (size_t)row * H + h4);
}

// ---------------------------------------------------------------------------
// GRU combine: sums split-K partials + biases, computes gates, fans out h_new
// ---------------------------------------------------------------------------
__global__ void __launch_bounds__(256) gru_combine(
    const float *__restrict__ hprev, const float *__restrict__ b_ih,
    const float *__restrict__ b_hh, float *__restrict__ out_hidden) {
    int idx = blockIdx.x * 256 + threadIdx.x;  // B*H/4
    int b = idx >> 8;
    int h4 = (idx & 255) << 2;

    float4 gx[3], gh[3];
#pragma unroll
    for (int g = 0; g < 3; g++) {
        gx[g] = *(const float4 *)(b_ih + g * H + h4);
        gh[g] = *(const float4 *)(b_hh + g * H + h4);
#pragma unroll
        for (int s = 0; s < S_GRU; s++) {
            size_t off = ((size_t)s * B + b) * 3 * H + g * H + h4;
            float4 px = *(const float4 *)(g_gxp + off);
            float4 ph = *(const float4 *)(g_ghp + off);
            gx[g].x += px.x; gx[g].y += px.y; gx[g].z += px.z; gx[g].w += px.w;
            gh[g].x += ph.x; gh[g].y += ph.y; gh[g].z += ph.z; gh[g].w += ph.w;
        }
    }
    float4 hp = *(const float4 *)(hprev + b * H + h4);
    float4 ho;
#pragma unroll
    for (int j = 0; j < 4; j++) {
        float xr = (&gx[0].x)[j], xz = (&gx[1].x)[j], xn = (&gx[2].x)[j];
        float hr = (&gh[0].x)[j], hz = (&gh[1].x)[j], hn = (&gh[2].x)[j];
        float r = 1.f / (1.f + expf(-(xr + hr)));
        float z = 1.f / (1.f + expf(-(xz + hz)));
        float n = tanhf(xn + r * hn);
        (&ho.x)[j] = (1.f - z) * n + z * (&hp.x)[j];
    }
    *(float4 *)(g_hnew + b * H + h4) = ho;
    *(float4 *)(out_hidden + b * H + h4) = ho;
    *(float4 *)(g_concat_in + b * 2 * H + h4) = ho;
}

// ---------------------------------------------------------------------------
// Attention scores: h in registers as f32x2 pairs; 8 warps x 8 t per CTA.
// ---------------------------------------------------------------------------
__global__ void __launch_bounds__(256) scores_kernel(const float *__restrict__ enc) {
    const int b = blockIdx.y;
    const int t0 = blockIdx.x * 64;
    const int tid = threadIdx.x;
    const int warp = tid >> 5, lane = tid & 31;

    const float *hb = g_hnew + b * H + lane * 4;
    ulonglong2 hv[8];
#pragma unroll
    for (int i = 0; i < 8; i++) hv[i] = *(const ulonglong2 *)(hb + i * 128);

#pragma unroll
    for (int it = 0; it < 8; it++) {
        int t = t0 + warp * 8 + it;
        const float *e = enc + ((size_t)t * B + b) * H + lane * 4;
        u64 acc = 0ull;
#pragma unroll
        for (int i = 0; i < 8; i++) {
            ulonglong2 ev = *(const ulonglong2 *)(e + i * 128);
            FMA2(acc, ev.x, hv[i].x, acc);
            FMA2(acc, ev.y, hv[i].y, acc);
        }
        float lo, hi;
        unpack2(acc, lo, hi);
        float s = lo + hi;
#pragma unroll
        for (int o = 16; o; o >>= 1) s += __shfl_xor_sync(0xffffffffu, s, o);
        if (!lane) g_scores[b * T + t] = s;
    }
}

// ---------------------------------------------------------------------------
// Softmax over T per batch row
// ---------------------------------------------------------------------------
__global__ void __launch_bounds__(256) softmax_kernel(float *__restrict__ attn_out) {
    const int b = blockIdx.x;
    const int tid = threadIdx.x;
    const int lane = tid & 31, wid = tid >> 5;
    __shared__ float red[8];
    float4 s = *(const float4 *)(g_scores + b * T + tid * 4);
    float m = fmaxf(fmaxf(s.x, s.y), fmaxf(s.z, s.w));
#pragma unroll
    for (int o = 16; o; o >>= 1) m = fmaxf(m, __shfl_xor_sync(0xffffffffu, m, o));
    if (!lane) red[wid] = m;
    __syncthreads();
    float bm = red[0];
#pragma unroll
    for (int i = 1; i < 8; i++) bm = fmaxf(bm, red[i]);
    float e0 = expf(s.x - bm), e1 = expf(s.y - bm);
    float e2 = expf(s.z - bm), e3 = expf(s.w - bm);
    float ssum = e0 + e1 + e2 + e3;
#pragma unroll
    for (int o = 16; o; o >>= 1) ssum += __shfl_xor_sync(0xffffffffu, ssum, o);
    __syncthreads();
    if (!lane) red[wid] = ssum;
    __syncthreads();
    float tot = 0.f;
#pragma unroll
    for (int i = 0; i < 8; i++) tot += red[i];
    float inv = 1.f / tot;
    float4 p = make_float4(e0 * inv, e1 * inv, e2 * inv, e3 * inv);
    *(float4 *)(g_attn + b * T + tid * 4) = p;
    *(float4 *)(attn_out + b * T + tid * 4) = p;
}

// ---------------------------------------------------------------------------
// Context partials: grid (8 t-chunks, 16 b-groups); thread = (b, 16 h), f32x2.
// ---------------------------------------------------------------------------
__global__ void __launch_bounds__(256) ctx_partial(const float *__restrict__ enc) {
    const int chunk = blockIdx.x;
    const int bg = blockIdx.y * 4;
    const int tid = threadIdx.x;
    __shared__ float wsd[4][256];  // duplicated attn weights

    for (int i = tid; i < 512; i += 256) {
        int bi = i >> 7, ti = i & 127;
        float w = g_attn[(bg + bi) * T + chunk * 128 + ti];
        *(u64 *)&wsd[bi][2 * ti] = pack2(w, w);
    }
    __syncthreads();

    const int bloc = tid >> 6;
    const int b = bg + bloc;
    const int hb = (tid & 63) << 4;

    u64 acc[8];
#pragma unroll
    for (int i = 0; i < 8; i++) acc[i] = 0ull;

    const float *ebase = enc + (((size_t)chunk * 128) * B + b) * H + hb;
#pragma unroll 4
    for (int t = 0; t < 128; t++) {
        const ulonglong2 *ep = (const ulonglong2 *)(ebase + (size_t)t * B * H);
        u64 w = *(const u64 *)&wsd[bloc][2 * t];
        ulonglong2 e0 = ep[0], e1 = ep[1], e2 = ep[2], e3 = ep[3];
        FMA2(acc[0], w, e0.x, acc[0]);
        FMA2(acc[1], w, e0.y, acc[1]);
        FMA2(acc[2], w, e1.x, acc[2]);
        FMA2(acc[3], w, e1.y, acc[3]);
        FMA2(acc[4], w, e2.x, acc[4]);
        FMA2(acc[5], w, e2.y, acc[5]);
        FMA2(acc[6], w, e3.x, acc[6]);
        FMA2(acc[7], w, e3.y, acc[7]);
    }
    float v[16];
#pragma unroll
    for (int i = 0; i < 8; i++) unpack2(acc[i], v[2 * i], v[2 * i + 1]);
    float *cp = g_ctxpart + ((size_t)b * 8 + chunk) * H + hb;
#pragma unroll
    for (int i = 0; i < 4; i++)
        *(float4 *)(cp + 4 * i) =
            make_float4(v[4 * i], v[4 * i + 1], v[4 * i + 2], v[4 * i + 3]);
}

// ---------------------------------------------------------------------------
// Reduce context partials into concat_in[:, H:2H]
// ---------------------------------------------------------------------------
__global__ void __launch_bounds__(256) ctx_reduce() {
    int idx = blockIdx.x * 256 + threadIdx.x;  // B*H/4
    int b = idx >> 8;
    int h4 = (idx & 255) << 2;
    float4 s = make_float4(0.f, 0.f, 0.f, 0.f);
#pragma unroll
    for (int j = 0; j < 8; j++) {
        float4 p = *(const float4 *)(g_ctxpart + ((size_t)b * 8 + j) * H + h4);
        s.x += p.x; s.y += p.y; s.z += p.z; s.w += p.w;
    }
    *(float4 *)(g_concat_in + b * 2 * H + H + h4) = s;
}

// ---------------------------------------------------------------------------
// Concat reduce: sum split-K partials + bias, tanh -> g_concat_out
// ---------------------------------------------------------------------------
__global__ void __launch_bounds__(256) concat_reduce(const float *__restrict__ cb) {
    int idx = blockIdx.x * 256 + threadIdx.x;  // B*H/4
    int b = idx >> 8;
    int h4 = (idx & 255) << 2;
    float4 s = *(const float4 *)(cb + h4);
#pragma unroll
    for (int j = 0; j < S_CAT; j++) {
        float4 p = *(const float4 *)(g_cp + ((size_t)j * B + b) * H + h4);
        s.x += p.x; s.y += p.y; s.z += p.z; s.w += p.w;
    }
    s.x = tanhf(s.x); s.y = tanhf(s.y); s.z = tanhf(s.z); s.w = tanhf(s.w);
    *(float4 *)(g_concat_out + b * H + h4) = s;
}

// ---------------------------------------------------------------------------
extern "C" void kernel_launch(void *const *d_in, const int *in_sizes, int n_in,
                              void *d_out, int out_size) {
    const int *seq     = (const int *)d_in[0];
    const float *hprev = (const float *)d_in[1];
    const float *enc   = (const float *)d_in[2];
    const float *emb   = (const float *)d_in[3];
    const float *w_ih  = (const float *)d_in[4];
    const float *w_hh  = (const float *)d_in[5];
    const float *b_ih  = (const float *)d_in[6];
    const float *b_hh  = (const float *)d_in[7];
    const float *cW    = (const float *)d_in[8];
    const float *cb    = (const float *)d_in[9];
    const float *oW    = (const float *)d_in[10];
    const float *ob    = (const float *)d_in[11];
    float *out = (float *)d_out;

    float *p_emb, *p_gxp, *p_ghp, *p_cin, *p_cp, *p_cout;
    cudaGetSymbolAddress((void **)&p_emb,  g_emb);
    cudaGetSymbolAddress((void **)&p_gxp,  g_gxp);
    cudaGetSymbolAddress((void **)&p_ghp,  g_ghp);
    cudaGetSymbolAddress((void **)&p_cin,  g_concat_in);
    cudaGetSymbolAddress((void **)&p_cp,   g_cp);
    cudaGetSymbolAddress((void **)&p_cout, g_concat_out);

    float *out_hidden = out + (size_t)B * V;
    float *out_attn   = out + (size_t)B * V + (size_t)B * H;

    // 1) embedding gather
    gather_emb<<<64, 256>>>(seq, emb);
    // 2) both GRU GEMMs fused in one launch, split-K=4 (grid 24 x 4 x 2)
    gemm128<<<dim3(3 * H / 128, S_GRU, 2), 256>>>(
        w_ih, p_emb, w_hh, hprev, nullptr, p_gxp, p_ghp, 3 * H, H, H / S_GRU);
    // 3) gate combine (+ split-K reduce + biases)
    gru_combine<<<64, 256>>>(hprev, b_ih, b_hh, out_hidden);
    // 4) attention scores
    scores_kernel<<<dim3(T / 64, B), 256>>>(enc);
    // 5) softmax
    softmax_kernel<<<B, 256>>>(out_attn);
    // 6/7) context
    ctx_partial<<<dim3(8, B / 4), 256>>>(enc);
    ctx_reduce<<<64, 256>>>();
    // 8) concat GEMM split-K=16 (grid 8 x 16), tanh+bias in reduce
    gemm128<<<dim3(H / 128, S_CAT, 1), 256>>>(
        cW, p_cin, cW, p_cin, nullptr, p_cp, p_cp, H, 2 * H, 2 * H / S_CAT);
    concat_reduce<<<64, 256>>>(cb);
    // 9) output GEMM: V x B, K = H, bias fused
    gemm128<<<dim3(V / 128, 1, 1), 256>>>(
        oW, p_cout, oW, p_cout, ob, out, out, V, H, H);
}

// round 3
// speedup vs baseline: 1.2450x; 1.1073x over previous
#include <cuda_runtime.h>
#include <math.h>

#define B 64
#define H 1024
#define T 1024
#define V 32000

#define S_GRU 4   // split-K for GRU gemms (K=1024 -> chunks of 256)
#define S_CAT 16  // split-K for concat gemm (K=2048 -> chunks of 128)
#define NCHUNK 4  // attention t-chunks (256 t each)

// ---------------- scratch (alloc-free: __device__ globals) ----------------
__device__ float g_emb[B * H];
__device__ float g_gxp[S_GRU * B * 3 * H];
__device__ float g_ghp[S_GRU * B * 3 * H];
__device__ float g_hnew[B * H];
__device__ float g_scores[B * T];
__device__ float g_pm[B * NCHUNK];
__device__ float g_ps[B * NCHUNK];
__device__ float g_ctxpart[B * NCHUNK * H];
__device__ float g_concat_in[B * 2 * H];
__device__ float g_cp[S_CAT * B * H];
__device__ float g_concat_out[B * H];

typedef unsigned long long u64;

__device__ __forceinline__ u64 pack2(float lo, float hi) {
    u64 r;
    asm("mov.b64 %0, {%1, %2};" : "=l"(r) : "f"(lo), "f"(hi));
    return r;
}
__device__ __forceinline__ void unpack2(u64 v, float &lo, float &hi) {
    asm("mov.b64 {%0, %1}, %2;" : "=f"(lo), "=f"(hi) : "l"(v));
}
#define FMA2(d, a, b, c) \
    asm("fma.rn.f32x2 %0, %1, %2, %3;" : "=l"(d) : "l"(a), "l"(b), "l"(c))

// ---------------------------------------------------------------------------
// GEMM: C[gy*64*M + n*M + m] = sum_{k in chunk gy} W[m*K+k] * X[n*K+k] (+bias)
// CTA tile 128m x 64n, 256 threads, thread tile 8m x 4n, f32x2 accumulators.
// blockIdx.z==1 selects the second (W2,X2,C2) problem (fused GRU launch).
// ---------------------------------------------------------------------------
__global__ void __launch_bounds__(256, 2) gemm128(
    const float *__restrict__ W, const float *__restrict__ X,
    const float *__restrict__ W2, const float *__restrict__ X2,
    const float *__restrict__ bias, float *C, float *C2,
    int M, int K, int kChunk) {
    __shared__ float As[16][128];
    __shared__ float Xd[16][128];
    if (blockIdx.z == 1) { W = W2; X = X2; C = C2; }
    const int tid = threadIdx.x;
    const int mBase = blockIdx.x * 128;
    const int kBase = blockIdx.y * kChunk;
    C += (size_t)blockIdx.y * 64 * M;

    const int ty = tid >> 4;         // m group (0..15) -> 8 m each
    const int tx = tid & 15;         // n group -> 4 n each
    const int lm = tid & 127;        // A loader: m row
    const int lka = (tid >> 7) << 3; // A loader: k off 0/8
    const int ln = tid & 63;         // X loader: n row
    const int lkx = (tid >> 6) << 2; // X loader: k off 0,4,8,12

    const float *Wp = W + (size_t)(mBase + lm) * K + kBase + lka;
    const float *Xp = X + (size_t)ln * K + kBase + lkx;

    float4 wa0 = *(const float4 *)Wp;
    float4 wa1 = *(const float4 *)(Wp + 4);
    float4 xr  = *(const float4 *)Xp;

    u64 acc[4][4];
#pragma unroll
    for (int i = 0; i < 4; i++)
#pragma unroll
        for (int j = 0; j < 4; j++) acc[i][j] = 0ull;

    const int NT = kChunk >> 4;
    for (int kt = 0; kt < NT; ++kt) {
        __syncthreads();
        As[lka + 0][lm] = wa0.x; As[lka + 1][lm] = wa0.y;
        As[lka + 2][lm] = wa0.z; As[lka + 3][lm] = wa0.w;
        As[lka + 4][lm] = wa1.x; As[lka + 5][lm] = wa1.y;
        As[lka + 6][lm] = wa1.z; As[lka + 7][lm] = wa1.w;
        *(u64 *)&Xd[lkx + 0][2 * ln] = pack2(xr.x, xr.x);
        *(u64 *)&Xd[lkx + 1][2 * ln] = pack2(xr.y, xr.y);
        *(u64 *)&Xd[lkx + 2][2 * ln] = pack2(xr.z, xr.z);
        *(u64 *)&Xd[lkx + 3][2 * ln] = pack2(xr.w, xr.w);
        __syncthreads();
        if (kt + 1 < NT) {
            wa0 = *(const float4 *)(Wp + (kt + 1) * 16);
            wa1 = *(const float4 *)(Wp + (kt + 1) * 16 + 4);
            xr  = *(const float4 *)(Xp + (kt + 1) * 16);
        }
#pragma unroll
        for (int k = 0; k < 16; ++k) {
            const ulonglong2 *ar = (const ulonglong2 *)&As[k][ty << 3];
            ulonglong2 a01 = ar[0], a23 = ar[1];
            const ulonglong2 *xp = (const ulonglong2 *)&Xd[k][tx << 3];
            ulonglong2 x01 = xp[0], x23 = xp[1];
            FMA2(acc[0][0], a01.x, x01.x, acc[0][0]);
            FMA2(acc[0][1], a01.x, x01.y, acc[0][1]);
            FMA2(acc[0][2], a01.x, x23.x, acc[0][2]);
            FMA2(acc[0][3], a01.x, x23.y, acc[0][3]);
            FMA2(acc[1][0], a01.y, x01.x, acc[1][0]);
            FMA2(acc[1][1], a01.y, x01.y, acc[1][1]);
            FMA2(acc[1][2], a01.y, x23.x, acc[1][2]);
            FMA2(acc[1][3], a01.y, x23.y, acc[1][3]);
            FMA2(acc[2][0], a23.x, x01.x, acc[2][0]);
            FMA2(acc[2][1], a23.x, x01.y, acc[2][1]);
            FMA2(acc[2][2], a23.x, x23.x, acc[2][2]);
            FMA2(acc[2][3], a23.x, x23.y, acc[2][3]);
            FMA2(acc[3][0], a23.y, x01.x, acc[3][0]);
            FMA2(acc[3][1], a23.y, x01.y, acc[3][1]);
            FMA2(acc[3][2], a23.y, x23.x, acc[3][2]);
            FMA2(acc[3][3], a23.y, x23.y, acc[3][3]);
        }
    }

    float cv[8][4];
#pragma unroll
    for (int mp = 0; mp < 4; mp++)
#pragma unroll
        for (int nj = 0; nj < 4; nj++)
            unpack2(acc[mp][nj], cv[mp * 2][nj], cv[mp * 2 + 1][nj]);

    float bb[8];
    if (bias) {
        float4 b0 = *(const float4 *)(bias + mBase + (ty << 3));
        float4 b1 = *(const float4 *)(bias + mBase + (ty << 3) + 4);
        bb[0] = b0.x; bb[1] = b0.y; bb[2] = b0.z; bb[3] = b0.w;
        bb[4] = b1.x; bb[5] = b1.y; bb[6] = b1.z; bb[7] = b1.w;
    } else {
#pragma unroll
        for (int i = 0; i < 8; i++) bb[i] = 0.f;
    }
#pragma unroll
    for (int nj = 0; nj < 4; nj++) {
        float *cp = C + (size_t)((tx << 2) + nj) * M + mBase + (ty << 3);
        float4 v0 = make_float4(cv[0][nj] + bb[0], cv[1][nj] + bb[1],
                                cv[2][nj] + bb[2], cv[3][nj] + bb[3]);
        float4 v1 = make_float4(cv[4][nj] + bb[4], cv[5][nj] + bb[5],
                                cv[6][nj] + bb[6], cv[7][nj] + bb[7]);
        *(float4 *)cp = v0;
        *(float4 *)(cp + 4) = v1;
    }
}

// ---------------------------------------------------------------------------
// Embedding gather
// ---------------------------------------------------------------------------
__global__ void __launch_bounds__(256) gather_emb(
    const int *__restrict__ seq, const float *__restrict__ emb_table) {
    int idx = blockIdx.x * 256 + threadIdx.x;  // B*H/4
    int b = idx >> 8;
    int h4 = (idx & 255) << 2;
    int row = seq[b];
    *(float4 *)(g_emb + b * H + h4) =
        *(const float4 *)(emb_table + (size_t)row * H + h4);
}

// ---------------------------------------------------------------------------
// GRU combine: sums split-K partials + biases, computes gates, fans out h_new
// ---------------------------------------------------------------------------
__global__ void __launch_bounds__(256) gru_combine(
    const float *__restrict__ hprev, const float *__restrict__ b_ih,
    const float *__restrict__ b_hh, float *__restrict__ out_hidden) {
    int idx = blockIdx.x * 256 + threadIdx.x;  // B*H/4
    int b = idx >> 8;
    int h4 = (idx & 255) << 2;

    float4 gx[3], gh[3];
#pragma unroll
    for (int g = 0; g < 3; g++) {
        gx[g] = *(const float4 *)(b_ih + g * H + h4);
        gh[g] = *(const float4 *)(b_hh + g * H + h4);
#pragma unroll
        for (int s = 0; s < S_GRU; s++) {
            size_t off = ((size_t)s * B + b) * 3 * H + g * H + h4;
            float4 px = *(const float4 *)(g_gxp + off);
            float4 ph = *(const float4 *)(g_ghp + off);
            gx[g].x += px.x; gx[g].y += px.y; gx[g].z += px.z; gx[g].w += px.w;
            gh[g].x += ph.x; gh[g].y += ph.y; gh[g].z += ph.z; gh[g].w += ph.w;
        }
    }
    float4 hp = *(const float4 *)(hprev + b * H + h4);
    float4 ho;
#pragma unroll
    for (int j = 0; j < 4; j++) {
        float xr = (&gx[0].x)[j], xz = (&gx[1].x)[j], xn = (&gx[2].x)[j];
        float hr = (&gh[0].x)[j], hz = (&gh[1].x)[j], hn = (&gh[2].x)[j];
        float r = 1.f / (1.f + expf(-(xr + hr)));
        float z = 1.f / (1.f + expf(-(xz + hz)));
        float n = tanhf(xn + r * hn);
        (&ho.x)[j] = (1.f - z) * n + z * (&hp.x)[j];
    }
    *(float4 *)(g_hnew + b * H + h4) = ho;
    *(float4 *)(out_hidden + b * H + h4) = ho;
    *(float4 *)(g_concat_in + b * 2 * H + h4) = ho;
}

// ---------------------------------------------------------------------------
// Fused attention pass 1: scores + online softmax + context partials.
// grid (NCHUNK, B), 256 threads. Each CTA handles 256 timesteps of one b,
// in blocks of 32 t: score-phase (warps do 4 dots each), then ctx-phase
// (re-reads the hot 128KB enc block from L1/L2). Single DRAM pass over enc.
// ---------------------------------------------------------------------------
__global__ void __launch_bounds__(256, 2) attn_partial(const float *__restrict__ enc) {
    const int b = blockIdx.y;
    const int chunk = blockIdx.x;
    const int t0 = chunk * 256;
    const int tid = threadIdx.x;
    const int warp = tid >> 5, lane = tid & 31;

    __shared__ float sblk[32];
    __shared__ float eblk[32];

    // h for this b, register-resident as f32x2 pairs (per-lane slice)
    const float *hb = g_hnew + b * H + lane * 4;
    ulonglong2 hv[8];
#pragma unroll
    for (int i = 0; i < 8; i++) hv[i] = *(const ulonglong2 *)(hb + i * 128);

    float M = -1e30f, S = 0.f;
    float4 cacc = make_float4(0.f, 0.f, 0.f, 0.f);
    const float *ebase = enc + ((size_t)t0 * B + b) * H;

    for (int blk = 0; blk < 8; blk++) {
        const int tb = blk * 32;
        // --- score phase: this warp computes 4 t's ---
        float sq[4];
#pragma unroll
        for (int q = 0; q < 4; q++) {
            const int tl = tb + warp * 4 + q;
            const float *e = ebase + (size_t)tl * B * H + lane * 4;
            u64 acc = 0ull;
#pragma unroll
            for (int i = 0; i < 8; i++) {
                ulonglong2 ev = *(const ulonglong2 *)(e + i * 128);
                FMA2(acc, ev.x, hv[i].x, acc);
                FMA2(acc, ev.y, hv[i].y, acc);
            }
            float lo, hi;
            unpack2(acc, lo, hi);
            float s = lo + hi;
#pragma unroll
            for (int o = 16; o; o >>= 1) s += __shfl_xor_sync(0xffffffffu, s, o);
            sq[q] = s;
            if (!lane) g_scores[b * T + t0 + tl] = s;
        }
        if (!lane) {
            sblk[warp * 4 + 0] = sq[0]; sblk[warp * 4 + 1] = sq[1];
            sblk[warp * 4 + 2] = sq[2]; sblk[warp * 4 + 3] = sq[3];
        }
        __syncthreads();
        // --- online softmax update (uniform across CTA) ---
        float m_blk = sblk[0];
#pragma unroll
        for (int i = 1; i < 32; i++) m_blk = fmaxf(m_blk, sblk[i]);
        float Mn = fmaxf(M, m_blk);
        float r = expf(M - Mn);
        if (tid < 32) eblk[tid] = expf(sblk[tid] - Mn);
        __syncthreads();
        float es = 0.f;
#pragma unroll
        for (int i = 0; i < 32; i++) es += eblk[i];
        S = S * r + es;
        M = Mn;
        // --- context phase: re-read hot enc block ---
        cacc.x *= r; cacc.y *= r; cacc.z *= r; cacc.w *= r;
        const float *e2 = ebase + (size_t)tb * B * H + tid * 4;
#pragma unroll 8
        for (int t = 0; t < 32; t++) {
            float w = eblk[t];
            float4 ev = *(const float4 *)(e2 + (size_t)t * B * H);
            cacc.x += w * ev.x; cacc.y += w * ev.y;
            cacc.z += w * ev.z; cacc.w += w * ev.w;
        }
        __syncthreads();  // sblk/eblk reuse next block
    }

    *(float4 *)(g_ctxpart + ((size_t)b * NCHUNK + chunk) * H + tid * 4) = cacc;
    if (tid == 0) {
        g_pm[b * NCHUNK + chunk] = M;
        g_ps[b * NCHUNK + chunk] = S;
    }
}

// ---------------------------------------------------------------------------
// Fused attention pass 2: combine chunk partials; write context into
// concat_in[:, H:2H] and exact softmax weights into out_attn.
// grid (B), 256 threads.
// ---------------------------------------------------------------------------
__global__ void __launch_bounds__(256) attn_combine(float *__restrict__ attn_out) {
    const int b = blockIdx.x;
    const int tid = threadIdx.x;

    float m[NCHUNK], s[NCHUNK];
#pragma unroll
    for (int j = 0; j < NCHUNK; j++) {
        m[j] = g_pm[b * NCHUNK + j];
        s[j] = g_ps[b * NCHUNK + j];
    }
    float gm = m[0];
#pragma unroll
    for (int j = 1; j < NCHUNK; j++) gm = fmaxf(gm, m[j]);
    float gsum = 0.f;
    float f[NCHUNK];
#pragma unroll
    for (int j = 0; j < NCHUNK; j++) {
        f[j] = expf(m[j] - gm);
        gsum += f[j] * s[j];
    }
    float inv = 1.f / gsum;

    // context
    int h4 = tid * 4;
    float4 c = make_float4(0.f, 0.f, 0.f, 0.f);
#pragma unroll
    for (int j = 0; j < NCHUNK; j++) {
        float4 p = *(const float4 *)(g_ctxpart + ((size_t)b * NCHUNK + j) * H + h4);
        float fj = f[j] * inv;
        c.x += fj * p.x; c.y += fj * p.y; c.z += fj * p.z; c.w += fj * p.w;
    }
    *(float4 *)(g_concat_in + b * 2 * H + H + h4) = c;

    // attention weights from raw scores
    float4 sc = *(const float4 *)(g_scores + b * T + tid * 4);
    float4 a = make_float4(expf(sc.x - gm) * inv, expf(sc.y - gm) * inv,
                           expf(sc.z - gm) * inv, expf(sc.w - gm) * inv);
    *(float4 *)(attn_out + b * T + tid * 4) = a;
}

// ---------------------------------------------------------------------------
// Concat reduce: sum split-K partials + bias, tanh -> g_concat_out
// ---------------------------------------------------------------------------
__global__ void __launch_bounds__(256) concat_reduce(const float *__restrict__ cb) {
    int idx = blockIdx.x * 256 + threadIdx.x;  // B*H/4
    int b = idx >> 8;
    int h4 = (idx & 255) << 2;
    float4 s = *(const float4 *)(cb + h4);
#pragma unroll
    for (int j = 0; j < S_CAT; j++) {
        float4 p = *(const float4 *)(g_cp + ((size_t)j * B + b) * H + h4);
        s.x += p.x; s.y += p.y; s.z += p.z; s.w += p.w;
    }
    s.x = tanhf(s.x); s.y = tanhf(s.y); s.z = tanhf(s.z); s.w = tanhf(s.w);
    *(float4 *)(g_concat_out + b * H + h4) = s;
}

// ---------------------------------------------------------------------------
extern "C" void kernel_launch(void *const *d_in, const int *in_sizes, int n_in,
                              void *d_out, int out_size) {
    const int *seq     = (const int *)d_in[0];
    const float *hprev = (const float *)d_in[1];
    const float *enc   = (const float *)d_in[2];
    const float *emb   = (const float *)d_in[3];
    const float *w_ih  = (const float *)d_in[4];
    const float *w_hh  = (const float *)d_in[5];
    const float *b_ih  = (const float *)d_in[6];
    const float *b_hh  = (const float *)d_in[7];
    const float *cW    = (const float *)d_in[8];
    const float *cb    = (const float *)d_in[9];
    const float *oW    = (const float *)d_in[10];
    const float *ob    = (const float *)d_in[11];
    float *out = (float *)d_out;

    float *p_emb, *p_gxp, *p_ghp, *p_cin, *p_cp, *p_cout;
    cudaGetSymbolAddress((void **)&p_emb,  g_emb);
    cudaGetSymbolAddress((void **)&p_gxp,  g_gxp);
    cudaGetSymbolAddress((void **)&p_ghp,  g_ghp);
    cudaGetSymbolAddress((void **)&p_cin,  g_concat_in);
    cudaGetSymbolAddress((void **)&p_cp,   g_cp);
    cudaGetSymbolAddress((void **)&p_cout, g_concat_out);

    float *out_hidden = out + (size_t)B * V;
    float *out_attn   = out + (size_t)B * V + (size_t)B * H;

    // 1) embedding gather
    gather_emb<<<64, 256>>>(seq, emb);
    // 2) both GRU GEMMs fused, split-K=4
    gemm128<<<dim3(3 * H / 128, S_GRU, 2), 256>>>(
        w_ih, p_emb, w_hh, hprev, nullptr, p_gxp, p_ghp, 3 * H, H, H / S_GRU);
    // 3) gate combine (+ split-K reduce + biases)
    gru_combine<<<64, 256>>>(hprev, b_ih, b_hh, out_hidden);
    // 4) fused attention (scores + softmax + context), single enc pass
    attn_partial<<<dim3(NCHUNK, B), 256>>>(enc);
    attn_combine<<<B, 256>>>(out_attn);
    // 5) concat GEMM split-K=16, tanh+bias in reduce
    gemm128<<<dim3(H / 128, S_CAT, 1), 256>>>(
        cW, p_cin, cW, p_cin, nullptr, p_cp, p_cp, H, 2 * H, 2 * H / S_CAT);
    concat_reduce<<<64, 256>>>(cb);
    // 6) output GEMM: V x B, K = H, bias fused
    gemm128<<<dim3(V / 128, 1, 1), 256>>>(
        oW, p_cout, oW, p_cout, ob, out, out, V, H, H);
}

// round 10
// speedup vs baseline: 2.4692x; 1.9832x over previous
#include <cuda_runtime.h>
#include <cuda_bf16.h>
#include <math.h>
#include <stdint.h>

#define B 64
#define H 1024
#define T 1024
#define V 32000

#define S_GRU 4   // split-K for GRU gemms
#define S_CAT 16  // split-K for concat gemm
#define NCHUNK 4  // attention t-chunks (256 t each)

// ---------------- scratch (alloc-free: __device__ globals) ----------------
__device__ float g_emb[B * H];
__device__ float g_gxp[S_GRU * B * 3 * H];
__device__ float g_ghp[S_GRU * B * 3 * H];
__device__ float g_hnew[B * H];
__device__ float g_scores[B * T];
__device__ float g_pm[B * NCHUNK];
__device__ float g_ps[B * NCHUNK];
__device__ float g_ctxpart[B * NCHUNK * H];
__device__ float g_concat_in[B * 2 * H];
__device__ float g_cp[S_CAT * B * H];
__device__ float g_concat_out[B * H];
__device__ __nv_bfloat16 g_xhi[B * H];
__device__ __nv_bfloat16 g_xlo[B * H];

typedef unsigned long long u64;

__device__ __forceinline__ u64 pack2(float lo, float hi) {
    u64 r;
    asm("mov.b64 %0, {%1, %2};" : "=l"(r) : "f"(lo), "f"(hi));
    return r;
}
__device__ __forceinline__ void unpack2(u64 v, float &lo, float &hi) {
    asm("mov.b64 {%0, %1}, %2;" : "=f"(lo), "=f"(hi) : "l"(v));
}
#define FMA2(d, a, b, c) \
    asm("fma.rn.f32x2 %0, %1, %2, %3;" : "=l"(d) : "l"(a), "l"(b), "l"(c))

#define SWZ(o) ((o) ^ ((((uint32_t)(o)) >> 3) & 0x70))

#define MMA16816(d, a0, a1, a2, a3, b0, b1)                             \
    asm volatile(                                                       \
        "mma.sync.aligned.m16n8k16.row.col.f32.bf16.bf16.f32 "          \
        "{%0,%1,%2,%3}, {%4,%5,%6,%7}, {%8,%9}, {%0,%1,%2,%3};"         \
        : "+f"((d)[0]), "+f"((d)[1]), "+f"((d)[2]), "+f"((d)[3])        \
        : "r"(a0), "r"(a1), "r"(a2), "r"(a3), "r"(b0), "r"(b1))

// ---------------------------------------------------------------------------
// Output GEMM via mma.sync bf16 (split precision).
// C[n*V + m] = sum_k W[m,k] * X[n,k] + bias[m]
// CTA: 128m x 64n, K chunks of 64. 8 warps, each 32m x 32n (2x4 m16n8 tiles).
// D = Whi.Xhi + Wlo.Xhi + Whi.Xlo  (fp32 accumulate).
// ---------------------------------------------------------------------------
__global__ void __launch_bounds__(256) out_gemm_mma(
    const float *__restrict__ W, const float *__restrict__ bias,
    float *__restrict__ Cout) {
    // 16KB + 16KB + 8KB + 8KB = 48KB static smem
    __shared__ __align__(16) __nv_bfloat16 sAhi[128 * 64];
    __shared__ __align__(16) __nv_bfloat16 sAlo[128 * 64];
    __shared__ __align__(16) __nv_bfloat16 sBhi[64 * 64];
    __shared__ __align__(16) __nv_bfloat16 sBlo[64 * 64];

    const int tid = threadIdx.x;
    const int lane = tid & 31;
    const int warp = tid >> 5;
    const int mBase = blockIdx.x * 128;

    const int warpM = (warp & 3) * 32;
    const int warpN = (warp >> 2) * 32;
    const int gid = lane >> 2;   // 0..7
    const int tig = lane & 3;    // 0..3

    // loader indices
    const int rowA = tid >> 4;        // 0..15 (+16 per iter, 8 iters)
    const int kq = tid & 15;          // float4 within 64-k chunk
    const int rowB = tid >> 3;        // 0..31 (+32 per iter, 2 iters)
    const int qB = tid & 7;           // uint4 (8 halves) within 128B row

    float acc[2][4][4];
#pragma unroll
    for (int i = 0; i < 2; i++)
#pragma unroll
        for (int j = 0; j < 4; j++)
#pragma unroll
            for (int q = 0; q < 4; q++) acc[i][j][q] = 0.f;

    const char *cAhi = (const char *)sAhi;
    const char *cAlo = (const char *)sAlo;
    const char *cBhi = (const char *)sBhi;
    const char *cBlo = (const char *)sBlo;

    for (int c = 0; c < 16; ++c) {
        const int k0 = c * 64;
        // ---- global loads first (overlap previous chunk's MMA phase) ----
        float4 wv[8];
#pragma unroll
        for (int it = 0; it < 8; ++it) {
            int r = rowA + it * 16;
            wv[it] = *(const float4 *)(W + (size_t)(mBase + r) * H + k0 + kq * 4);
        }
        uint4 bh[2], bl[2];
#pragma unroll
        for (int it = 0; it < 2; ++it) {
            int r = rowB + it * 32;
            bh[it] = *(const uint4 *)(g_xhi + (size_t)r * H + k0 + qB * 8);
            bl[it] = *(const uint4 *)(g_xlo + (size_t)r * H + k0 + qB * 8);
        }
        __syncthreads();  // previous chunk fully consumed
        // ---- convert W -> bf16 hi/lo, store swizzled ----
#pragma unroll
        for (int it = 0; it < 8; ++it) {
            int r = rowA + it * 16;
            uint32_t off = SWZ((uint32_t)(r * 128 + kq * 8));
            __nv_bfloat162 h01 = __float22bfloat162_rn(make_float2(wv[it].x, wv[it].y));
            __nv_bfloat162 h23 = __float22bfloat162_rn(make_float2(wv[it].z, wv[it].w));
            float2 f01 = __bfloat1622float2(h01);
            float2 f23 = __bfloat1622float2(h23);
            __nv_bfloat162 l01 = __float22bfloat162_rn(
                make_float2(wv[it].x - f01.x, wv[it].y - f01.y));
            __nv_bfloat162 l23 = __float22bfloat162_rn(
                make_float2(wv[it].z - f23.x, wv[it].w - f23.y));
            *(uint2 *)((char *)sAhi + off) =
                make_uint2(*(uint32_t *)&h01, *(uint32_t *)&h23);
            *(uint2 *)((char *)sAlo + off) =
                make_uint2(*(uint32_t *)&l01, *(uint32_t *)&l23);
        }
#pragma unroll
        for (int it = 0; it < 2; ++it) {
            int r = rowB + it * 32;
            uint32_t off = SWZ((uint32_t)(r * 128 + qB * 16));
            *(uint4 *)((char *)sBhi + off) = bh[it];
            *(uint4 *)((char *)sBlo + off) = bl[it];
        }
        __syncthreads();
        // ---- 4 ksteps of K=16 ----
#pragma unroll
        for (int ks = 0; ks < 4; ++ks) {
            const int cb0 = ks * 32 + tig * 4;  // byte col of k-pair
            const int cb1 = cb0 + 16;
            // B fragments: 4 n-tiles, hi & lo
            uint32_t bhf[4][2], blf[4][2];
#pragma unroll
            for (int nt = 0; nt < 4; ++nt) {
                int rn = warpN + nt * 8 + gid;
                bhf[nt][0] = *(const uint32_t *)(cBhi + SWZ(rn * 128 + cb0));
                bhf[nt][1] = *(const uint32_t *)(cBhi + SWZ(rn * 128 + cb1));
                blf[nt][0] = *(const uint32_t *)(cBlo + SWZ(rn * 128 + cb0));
                blf[nt][1] = *(const uint32_t *)(cBlo + SWZ(rn * 128 + cb1));
            }
#pragma unroll
            for (int mt = 0; mt < 2; ++mt) {
                int r0 = warpM + mt * 16 + gid;
                uint32_t ah0 = *(const uint32_t *)(cAhi + SWZ(r0 * 128 + cb0));
                uint32_t ah1 = *(const uint32_t *)(cAhi + SWZ((r0 + 8) * 128 + cb0));
                uint32_t ah2 = *(const uint32_t *)(cAhi + SWZ(r0 * 128 + cb1));
                uint32_t ah3 = *(const uint32_t *)(cAhi + SWZ((r0 + 8) * 128 + cb1));
                uint32_t al0 = *(const uint32_t *)(cAlo + SWZ(r0 * 128 + cb0));
                uint32_t al1 = *(const uint32_t *)(cAlo + SWZ((r0 + 8) * 128 + cb0));
                uint32_t al2 = *(const uint32_t *)(cAlo + SWZ(r0 * 128 + cb1));
                uint32_t al3 = *(const uint32_t *)(cAlo + SWZ((r0 + 8) * 128 + cb1));
#pragma unroll
                for (int nt = 0; nt < 4; ++nt) {
                    MMA16816(acc[mt][nt], ah0, ah1, ah2, ah3, bhf[nt][0], bhf[nt][1]);
                    MMA16816(acc[mt][nt], al0, al1, al2, al3, bhf[nt][0], bhf[nt][1]);
                    MMA16816(acc[mt][nt], ah0, ah1, ah2, ah3, blf[nt][0], blf[nt][1]);
                }
            }
        }
    }

    // ---- epilogue: D[g][2tig], D[g][2tig+1], D[g+8][2tig], D[g+8][2tig+1] ----
#pragma unroll
    for (int mt = 0; mt < 2; ++mt) {
        int m0 = mBase + warpM + mt * 16 + gid;
        float bv0 = bias[m0], bv1 = bias[m0 + 8];
#pragma unroll
        for (int nt = 0; nt < 4; ++nt) {
            int n0 = warpN + nt * 8 + tig * 2;
            Cout[(size_t)n0 * V + m0]           = acc[mt][nt][0] + bv0;
            Cout[(size_t)(n0 + 1) * V + m0]     = acc[mt][nt][1] + bv0;
            Cout[(size_t)n0 * V + m0 + 8]       = acc[mt][nt][2] + bv1;
            Cout[(size_t)(n0 + 1) * V + m0 + 8] = acc[mt][nt][3] + bv1;
        }
    }
}

// ---------------------------------------------------------------------------
// Convert concat_out fp32 -> bf16 hi/lo pair for the MMA B operand
// ---------------------------------------------------------------------------
__global__ void __launch_bounds__(256) xconvert() {
    int idx = blockIdx.x * 256 + threadIdx.x;  // B*H/4 = 16384
    float4 x = *(const float4 *)(g_concat_out + idx * 4);
    __nv_bfloat162 h01 = __float22bfloat162_rn(make_float2(x.x, x.y));
    __nv_bfloat162 h23 = __float22bfloat162_rn(make_float2(x.z, x.w));
    float2 f01 = __bfloat1622float2(h01);
    float2 f23 = __bfloat1622float2(h23);
    __nv_bfloat162 l01 = __float22bfloat162_rn(make_float2(x.x - f01.x, x.y - f01.y));
    __nv_bfloat162 l23 = __float22bfloat162_rn(make_float2(x.z - f23.x, x.w - f23.y));
    *(uint2 *)(g_xhi + idx * 4) = make_uint2(*(uint32_t *)&h01, *(uint32_t *)&h23);
    *(uint2 *)(g_xlo + idx * 4) = make_uint2(*(uint32_t *)&l01, *(uint32_t *)&l23);
}

// ---------------------------------------------------------------------------
// FMA2 GEMM for the small problems (GRU, concat)
// ---------------------------------------------------------------------------
__global__ void __launch_bounds__(256, 2) gemm128(
    const float *__restrict__ W, const float *__restrict__ X,
    const float *__restrict__ W2, const float *__restrict__ X2,
    const float *__restrict__ bias, float *C, float *C2,
    int M, int K, int kChunk) {
    __shared__ float As[16][128];
    __shared__ float Xd[16][128];
    if (blockIdx.z == 1) { W = W2; X = X2; C = C2; }
    const int tid = threadIdx.x;
    const int mBase = blockIdx.x * 128;
    const int kBase = blockIdx.y * kChunk;
    C += (size_t)blockIdx.y * 64 * M;

    const int ty = tid >> 4;
    const int tx = tid & 15;
    const int lm = tid & 127;
    const int lka = (tid >> 7) << 3;
    const int ln = tid & 63;
    const int lkx = (tid >> 6) << 2;

    const float *Wp = W + (size_t)(mBase + lm) * K + kBase + lka;
    const float *Xp = X + (size_t)ln * K + kBase + lkx;

    float4 wa0 = *(const float4 *)Wp;
    float4 wa1 = *(const float4 *)(Wp + 4);
    float4 xr  = *(const float4 *)Xp;

    u64 acc[4][4];
#pragma unroll
    for (int i = 0; i < 4; i++)
#pragma unroll
        for (int j = 0; j < 4; j++) acc[i][j] = 0ull;

    const int NT = kChunk >> 4;
    for (int kt = 0; kt < NT; ++kt) {
        __syncthreads();
        As[lka + 0][lm] = wa0.x; As[lka + 1][lm] = wa0.y;
        As[lka + 2][lm] = wa0.z; As[lka + 3][lm] = wa0.w;
        As[lka + 4][lm] = wa1.x; As[lka + 5][lm] = wa1.y;
        As[lka + 6][lm] = wa1.z; As[lka + 7][lm] = wa1.w;
        *(u64 *)&Xd[lkx + 0][2 * ln] = pack2(xr.x, xr.x);
        *(u64 *)&Xd[lkx + 1][2 * ln] = pack2(xr.y, xr.y);
        *(u64 *)&Xd[lkx + 2][2 * ln] = pack2(xr.z, xr.z);
        *(u64 *)&Xd[lkx + 3][2 * ln] = pack2(xr.w, xr.w);
        __syncthreads();
        if (kt + 1 < NT) {
            wa0 = *(const float4 *)(Wp + (kt + 1) * 16);
            wa1 = *(const float4 *)(Wp + (kt + 1) * 16 + 4);
            xr  = *(const float4 *)(Xp + (kt + 1) * 16);
        }
#pragma unroll
        for (int k = 0; k < 16; ++k) {
            const ulonglong2 *ar = (const ulonglong2 *)&As[k][ty << 3];
            ulonglong2 a01 = ar[0], a23 = ar[1];
            const ulonglong2 *xp = (const ulonglong2 *)&Xd[k][tx << 3];
            ulonglong2 x01 = xp[0], x23 = xp[1];
            FMA2(acc[0][0], a01.x, x01.x, acc[0][0]);
            FMA2(acc[0][1], a01.x, x01.y, acc[0][1]);
            FMA2(acc[0][2], a01.x, x23.x, acc[0][2]);
            FMA2(acc[0][3], a01.x, x23.y, acc[0][3]);
            FMA2(acc[1][0], a01.y, x01.x, acc[1][0]);
            FMA2(acc[1][1], a01.y, x01.y, acc[1][1]);
            FMA2(acc[1][2], a01.y, x23.x, acc[1][2]);
            FMA2(acc[1][3], a01.y, x23.y, acc[1][3]);
            FMA2(acc[2][0], a23.x, x01.x, acc[2][0]);
            FMA2(acc[2][1], a23.x, x01.y, acc[2][1]);
            FMA2(acc[2][2], a23.x, x23.x, acc[2][2]);
            FMA2(acc[2][3], a23.x, x23.y, acc[2][3]);
            FMA2(acc[3][0], a23.y, x01.x, acc[3][0]);
            FMA2(acc[3][1], a23.y, x01.y, acc[3][1]);
            FMA2(acc[3][2], a23.y, x23.x, acc[3][2]);
            FMA2(acc[3][3], a23.y, x23.y, acc[3][3]);
        }
    }

    float cv[8][4];
#pragma unroll
    for (int mp = 0; mp < 4; mp++)
#pragma unroll
        for (int nj = 0; nj < 4; nj++)
            unpack2(acc[mp][nj], cv[mp * 2][nj], cv[mp * 2 + 1][nj]);

    float bb[8];
    if (bias) {
        float4 b0 = *(const float4 *)(bias + mBase + (ty << 3));
        float4 b1 = *(const float4 *)(bias + mBase + (ty << 3) + 4);
        bb[0] = b0.x; bb[1] = b0.y; bb[2] = b0.z; bb[3] = b0.w;
        bb[4] = b1.x; bb[5] = b1.y; bb[6] = b1.z; bb[7] = b1.w;
    } else {
#pragma unroll
        for (int i = 0; i < 8; i++) bb[i] = 0.f;
    }
#pragma unroll
    for (int nj = 0; nj < 4; nj++) {
        float *cp = C + (size_t)((tx << 2) + nj) * M + mBase + (ty << 3);
        float4 v0 = make_float4(cv[0][nj] + bb[0], cv[1][nj] + bb[1],
                                cv[2][nj] + bb[2], cv[3][nj] + bb[3]);
        float4 v1 = make_float4(cv[4][nj] + bb[4], cv[5][nj] + bb[5],
                                cv[6][nj] + bb[6], cv[7][nj] + bb[7]);
        *(float4 *)cp = v0;
        *(float4 *)(cp + 4) = v1;
    }
}

// ---------------------------------------------------------------------------
__global__ void __launch_bounds__(256) gather_emb(
    const int *__restrict__ seq, const float *__restrict__ emb_table) {
    int idx = blockIdx.x * 256 + threadIdx.x;
    int b = idx >> 8;
    int h4 = (idx & 255) << 2;
    int row = seq[b];
    *(float4 *)(g_emb + b * H + h4) =
        *(const float4 *)(emb_table + (size_t)row * H + h4);
}

// ---------------------------------------------------------------------------
__global__ void __launch_bounds__(256) gru_combine(
    const float *__restrict__ hprev, const float *__restrict__ b_ih,
    const float *__restrict__ b_hh, float *__restrict__ out_hidden) {
    int idx = blockIdx.x * 256 + threadIdx.x;
    int b = idx >> 8;
    int h4 = (idx & 255) << 2;

    float4 gx[3], gh[3];
#pragma unroll
    for (int g = 0; g < 3; g++) {
        gx[g] = *(const float4 *)(b_ih + g * H + h4);
        gh[g] = *(const float4 *)(b_hh + g * H + h4);
#pragma unroll
        for (int s = 0; s < S_GRU; s++) {
            size_t off = ((size_t)s * B + b) * 3 * H + g * H + h4;
            float4 px = *(const float4 *)(g_gxp + off);
            float4 ph = *(const float4 *)(g_ghp + off);
            gx[g].x += px.x; gx[g].y += px.y; gx[g].z += px.z; gx[g].w += px.w;
            gh[g].x += ph.x; gh[g].y += ph.y; gh[g].z += ph.z; gh[g].w += ph.w;
        }
    }
    float4 hp = *(const float4 *)(hprev + b * H + h4);
    float4 ho;
#pragma unroll
    for (int j = 0; j < 4; j++) {
        float xr = (&gx[0].x)[j], xz = (&gx[1].x)[j], xn = (&gx[2].x)[j];
        float hr = (&gh[0].x)[j], hz = (&gh[1].x)[j], hn = (&gh[2].x)[j];
        float r = 1.f / (1.f + expf(-(xr + hr)));
        float z = 1.f / (1.f + expf(-(xz + hz)));
        float n = tanhf(xn + r * hn);
        (&ho.x)[j] = (1.f - z) * n + z * (&hp.x)[j];
    }
    *(float4 *)(g_hnew + b * H + h4) = ho;
    *(float4 *)(out_hidden + b * H + h4) = ho;
    *(float4 *)(g_concat_in + b * 2 * H + h4) = ho;
}

// ---------------------------------------------------------------------------
// Fused attention pass 1
// ---------------------------------------------------------------------------
__global__ void __launch_bounds__(256, 2) attn_partial(const float *__restrict__ enc) {
    const int b = blockIdx.y;
    const int chunk = blockIdx.x;
    const int t0 = chunk * 256;
    const int tid = threadIdx.x;
    const int warp = tid >> 5, lane = tid & 31;

    __shared__ float sblk[32];
    __shared__ float eblk[32];

    const float *hb = g_hnew + b * H + lane * 4;
    ulonglong2 hv[8];
#pragma unroll
    for (int i = 0; i < 8; i++) hv[i] = *(const ulonglong2 *)(hb + i * 128);

    float M = -1e30f, S = 0.f;
    float4 cacc = make_float4(0.f, 0.f, 0.f, 0.f);
    const float *ebase = enc + ((size_t)t0 * B + b) * H;

    for (int blk = 0; blk < 8; blk++) {
        const int tb = blk * 32;
        float sq[4];
#pragma unroll
        for (int q = 0; q < 4; q++) {
            const int tl = tb + warp * 4 + q;
            const float *e = ebase + (size_t)tl * B * H + lane * 4;
            u64 acc = 0ull;
#pragma unroll
            for (int i = 0; i < 8; i++) {
                ulonglong2 ev = *(const ulonglong2 *)(e + i * 128);
                FMA2(acc, ev.x, hv[i].x, acc);
                FMA2(acc, ev.y, hv[i].y, acc);
            }
            float lo, hi;
            unpack2(acc, lo, hi);
            float s = lo + hi;
#pragma unroll
            for (int o = 16; o; o >>= 1) s += __shfl_xor_sync(0xffffffffu, s, o);
            sq[q] = s;
            if (!lane) g_scores[b * T + t0 + tl] = s;
        }
        if (!lane) {
            sblk[warp * 4 + 0] = sq[0]; sblk[warp * 4 + 1] = sq[1];
            sblk[warp * 4 + 2] = sq[2]; sblk[warp * 4 + 3] = sq[3];
        }
        __syncthreads();
        float m_blk = sblk[0];
#pragma unroll
        for (int i = 1; i < 32; i++) m_blk = fmaxf(m_blk, sblk[i]);
        float Mn = fmaxf(M, m_blk);
        float r = expf(M - Mn);
        if (tid < 32) eblk[tid] = expf(sblk[tid] - Mn);
        __syncthreads();
        float es = 0.f;
#pragma unroll
        for (int i = 0; i < 32; i++) es += eblk[i];
        S = S * r + es;
        M = Mn;
        cacc.x *= r; cacc.y *= r; cacc.z *= r; cacc.w *= r;
        const float *e2 = ebase + (size_t)tb * B * H + tid * 4;
#pragma unroll 8
        for (int t = 0; t < 32; t++) {
            float w = eblk[t];
            float4 ev = *(const float4 *)(e2 + (size_t)t * B * H);
            cacc.x += w * ev.x; cacc.y += w * ev.y;
            cacc.z += w * ev.z; cacc.w += w * ev.w;
        }
        __syncthreads();
    }

    *(float4 *)(g_ctxpart + ((size_t)b * NCHUNK + chunk) * H + tid * 4) = cacc;
    if (tid == 0) {
        g_pm[b * NCHUNK + chunk] = M;
        g_ps[b * NCHUNK + chunk] = S;
    }
}

// ---------------------------------------------------------------------------
__global__ void __launch_bounds__(256) attn_combine(float *__restrict__ attn_out) {
    const int b = blockIdx.x;
    const int tid = threadIdx.x;

    float m[NCHUNK], s[NCHUNK];
#pragma unroll
    for (int j = 0; j < NCHUNK; j++) {
        m[j] = g_pm[b * NCHUNK + j];
        s[j] = g_ps[b * NCHUNK + j];
    }
    float gm = m[0];
#pragma unroll
    for (int j = 1; j < NCHUNK; j++) gm = fmaxf(gm, m[j]);
    float gsum = 0.f;
    float f[NCHUNK];
#pragma unroll
    for (int j = 0; j < NCHUNK; j++) {
        f[j] = expf(m[j] - gm);
        gsum += f[j] * s[j];
    }
    float inv = 1.f / gsum;

    int h4 = tid * 4;
    float4 c = make_float4(0.f, 0.f, 0.f, 0.f);
#pragma unroll
    for (int j = 0; j < NCHUNK; j++) {
        float4 p = *(const float4 *)(g_ctxpart + ((size_t)b * NCHUNK + j) * H + h4);
        float fj = f[j] * inv;
        c.x += fj * p.x; c.y += fj * p.y; c.z += fj * p.z; c.w += fj * p.w;
    }
    *(float4 *)(g_concat_in + b * 2 * H + H + h4) = c;

    float4 sc = *(const float4 *)(g_scores + b * T + tid * 4);
    float4 a = make_float4(expf(sc.x - gm) * inv, expf(sc.y - gm) * inv,
                           expf(sc.z - gm) * inv, expf(sc.w - gm) * inv);
    *(float4 *)(attn_out + b * T + tid * 4) = a;
}

// ---------------------------------------------------------------------------
__global__ void __launch_bounds__(256) concat_reduce(const float *__restrict__ cb) {
    int idx = blockIdx.x * 256 + threadIdx.x;
    int b = idx >> 8;
    int h4 = (idx & 255) << 2;
    float4 s = *(const float4 *)(cb + h4);
#pragma unroll
    for (int j = 0; j < S_CAT; j++) {
        float4 p = *(const float4 *)(g_cp + ((size_t)j * B + b) * H + h4);
        s.x += p.x; s.y += p.y; s.z += p.z; s.w += p.w;
    }
    s.x = tanhf(s.x); s.y = tanhf(s.y); s.z = tanhf(s.z); s.w = tanhf(s.w);
    *(float4 *)(g_concat_out + b * H + h4) = s;
}

// ---------------------------------------------------------------------------
extern "C" void kernel_launch(void *const *d_in, const int *in_sizes, int n_in,
                              void *d_out, int out_size) {
    const int *seq     = (const int *)d_in[0];
    const float *hprev = (const float *)d_in[1];
    const float *enc   = (const float *)d_in[2];
    const float *emb   = (const float *)d_in[3];
    const float *w_ih  = (const float *)d_in[4];
    const float *w_hh  = (const float *)d_in[5];
    const float *b_ih  = (const float *)d_in[6];
    const float *b_hh  = (const float *)d_in[7];
    const float *cW    = (const float *)d_in[8];
    const float *cb    = (const float *)d_in[9];
    const float *oW    = (const float *)d_in[10];
    const float *ob    = (const float *)d_in[11];
    float *out = (float *)d_out;

    float *p_emb, *p_gxp, *p_ghp, *p_cin, *p_cp;
    cudaGetSymbolAddress((void **)&p_emb,  g_emb);
    cudaGetSymbolAddress((void **)&p_gxp,  g_gxp);
    cudaGetSymbolAddress((void **)&p_ghp,  g_ghp);
    cudaGetSymbolAddress((void **)&p_cin,  g_concat_in);
    cudaGetSymbolAddress((void **)&p_cp,   g_cp);

    float *out_hidden = out + (size_t)B * V;
    float *out_attn   = out + (size_t)B * V + (size_t)B * H;

    // 1) embedding gather
    gather_emb<<<64, 256>>>(seq, emb);
    // 2) both GRU GEMMs fused, split-K=4
    gemm128<<<dim3(3 * H / 128, S_GRU, 2), 256>>>(
        w_ih, p_emb, w_hh, hprev, nullptr, p_gxp, p_ghp, 3 * H, H, H / S_GRU);
    // 3) gate combine
    gru_combine<<<64, 256>>>(hprev, b_ih, b_hh, out_hidden);
    // 4) fused attention
    attn_partial<<<dim3(NCHUNK, B), 256>>>(enc);
    attn_combine<<<B, 256>>>(out_attn);
    // 5) concat GEMM split-K=16, tanh+bias in reduce
    gemm128<<<dim3(H / 128, S_CAT, 1), 256>>>(
        cW, p_cin, cW, p_cin, nullptr, p_cp, p_cp, H, 2 * H, 2 * H / S_CAT);
    concat_reduce<<<64, 256>>>(cb);
    // 6) X -> bf16 hi/lo for MMA
    xconvert<<<64, 256>>>();
    // 7) output GEMM on mma.sync bf16 (split precision)
    out_gemm_mma<<<V / 128, 256>>>(oW, ob, out);
}